// round 17
// baseline (speedup 1.0000x reference)
#include <cuda_runtime.h>

// NeuS volume-rendering composite, telescoped:
//   1 - alpha_i = sig_{i+1}/sig_i  =>  trans_i = sig_i / sig_0
//   weight_i = max(sig_i - sig_{i+1}, 0) / sig_0,  weight_0 = weight_{S-1} = 0.
//
// Software-pipelined PERSISTENT kernel (R11 retry, done right):
//   - grid = SMs x resident-blocks (queried at launch) -> zero tail waves
//   - per iteration: issue ALL 10 next-tile LDG.128 FIRST, then compute the
//     current tile whose loads were issued one full iteration (~1.8us) ago.
//     Cross-iteration MLP stays 10-deep; load latency is fully covered.
//   - __launch_bounds__(256,2): 128-reg budget for the double buffer
//     (2 x 10 float4 = 80 regs + working set), no spills, 16 warps/SM.
//     16 warps x 10 outstanding LDG.128 = 80KB in flight per SM >> ~18KB
//     needed to saturate the per-SM DRAM share.
//   - no __syncthreads anywhere: warps free-run, smoothing DRAM demand.
//
// 2 rays per warp (16-lane segments); sub-lane sl owns samples [4sl..4sl+3]
// and [64+4sl..64+4sl+3]. All bulk accesses aligned float4 (__ldg — R13
// showed streaming hints hurt). Background folded into the color sum.

constexpr int N_RAYS         = 65536;
constexpr int RAYS_PER_TILE  = 16;                   // 8 warps x 2 rays
constexpr int N_TILES        = N_RAYS / RAYS_PER_TILE;   // 4096

struct TileRegs {
    float4 sdA, sdB, zA, zB, cA0, cA1, cA2, cB0, cB1, cB2;
};

__device__ __forceinline__ float fsigmoid(float x) {
    return __fdividef(1.0f, 1.0f + __expf(-x));
}

__device__ __forceinline__ TileRegs load_tile(const float4* __restrict__ sp,
                                              const float4* __restrict__ zp,
                                              const float4* __restrict__ cbase,
                                              int ray, int sl)
{
    TileRegs t;
    const int r32 = ray * 32;
    const float4* cp = cbase + ray * 96 + sl * 3;
    t.sdA = __ldg(sp + r32 + sl);          // samples 4sl..4sl+3
    t.sdB = __ldg(sp + r32 + 16 + sl);     // samples 64+4sl..64+4sl+3
    t.zA  = __ldg(zp + r32 + sl);
    t.zB  = __ldg(zp + r32 + 16 + sl);
    t.cA0 = __ldg(cp + 0);                 // r0 g0 b0 r1
    t.cA1 = __ldg(cp + 1);                 // g1 b1 r2 g2
    t.cA2 = __ldg(cp + 2);                 // b2 r3 g3 b3
    t.cB0 = __ldg(cp + 48);
    t.cB1 = __ldg(cp + 49);
    t.cB2 = __ldg(cp + 50);
    return t;
}

__device__ __forceinline__ void process_tile(const TileRegs& T, int ray, int sl,
                                             float s, float bg0, float bg1, float bg2,
                                             float* __restrict__ out)
{
    const unsigned FULL = 0xffffffffu;
    const int r32 = ray * 32;

    // ---- sigmoids ----
    const float a0 = fsigmoid(T.sdA.x * s), a1 = fsigmoid(T.sdA.y * s);
    const float a2 = fsigmoid(T.sdA.z * s), a3 = fsigmoid(T.sdA.w * s);
    const float b0 = fsigmoid(T.sdB.x * s), b1 = fsigmoid(T.sdB.y * s);
    const float b2 = fsigmoid(T.sdB.z * s), b3 = fsigmoid(T.sdB.w * s);

    // ---- segment shuffles (width=16) ----
    const float a0_next  = __shfl_down_sync(FULL, a0, 1, 16);  // sig(4sl+4)
    const float b0_next  = __shfl_down_sync(FULL, b0, 1, 16);  // sig(64+4sl+4)
    const float b0_first = __shfl_sync(FULL, b0, 0, 16);       // sig(sample 64)
    const float sig0     = __shfl_sync(FULL, a0, 0, 16);       // sig(sample 0)
    const float inv_s0   = __fdividef(1.0f, sig0);

    const float nextA = (sl == 15) ? b0_first : a0_next;

    // ---- weights (weight_0 = 0, weight_127 = 0) ----
    const float wa0 = (sl == 0) ? 0.0f : fmaxf(a0 - a1, 0.0f) * inv_s0;
    const float wa1 = fmaxf(a1 - a2,    0.0f) * inv_s0;
    const float wa2 = fmaxf(a2 - a3,    0.0f) * inv_s0;
    const float wa3 = fmaxf(a3 - nextA, 0.0f) * inv_s0;
    const float wb0 = fmaxf(b0 - b1,    0.0f) * inv_s0;
    const float wb1 = fmaxf(b1 - b2,    0.0f) * inv_s0;
    const float wb2 = fmaxf(b2 - b3,    0.0f) * inv_s0;
    const float wb3 = (sl == 15) ? 0.0f : fmaxf(b3 - b0_next, 0.0f) * inv_s0;

    // ---- store weight tiles (aligned STG.128) ----
    float4* w_out = reinterpret_cast<float4*>(out + N_RAYS * 4);
    w_out[r32 + sl]      = make_float4(wa0, wa1, wa2, wa3);
    w_out[r32 + 16 + sl] = make_float4(wb0, wb1, wb2, wb3);

    // ---- inverse depth partial ----
    float invd = __fdividef(wa0, T.zA.x) + __fdividef(wa1, T.zA.y)
               + __fdividef(wa2, T.zA.z) + __fdividef(wa3, T.zA.w)
               + __fdividef(wb0, T.zB.x) + __fdividef(wb1, T.zB.y)
               + __fdividef(wb2, T.zB.z) + __fdividef(wb3, T.zB.w);

    // ---- pixel partials with background folded in ----
    float pr = wa0 * (T.cA0.x - bg0) + wa1 * (T.cA0.w - bg0)
             + wa2 * (T.cA1.z - bg0) + wa3 * (T.cA2.y - bg0)
             + wb0 * (T.cB0.x - bg0) + wb1 * (T.cB0.w - bg0)
             + wb2 * (T.cB1.z - bg0) + wb3 * (T.cB2.y - bg0);
    float pg = wa0 * (T.cA0.y - bg1) + wa1 * (T.cA1.x - bg1)
             + wa2 * (T.cA1.w - bg1) + wa3 * (T.cA2.z - bg1)
             + wb0 * (T.cB0.y - bg1) + wb1 * (T.cB1.x - bg1)
             + wb2 * (T.cB1.w - bg1) + wb3 * (T.cB2.z - bg1);
    float pb = wa0 * (T.cA0.z - bg2) + wa1 * (T.cA1.y - bg2)
             + wa2 * (T.cA2.x - bg2) + wa3 * (T.cA2.w - bg2)
             + wb0 * (T.cB0.z - bg2) + wb1 * (T.cB1.y - bg2)
             + wb2 * (T.cB2.x - bg2) + wb3 * (T.cB2.w - bg2);

    // ---- width-16 butterfly over 4 scalars ----
    #pragma unroll
    for (int off = 8; off > 0; off >>= 1) {
        pr   += __shfl_xor_sync(FULL, pr,   off, 16);
        pg   += __shfl_xor_sync(FULL, pg,   off, 16);
        pb   += __shfl_xor_sync(FULL, pb,   off, 16);
        invd += __shfl_xor_sync(FULL, invd, off, 16);
    }

    if (sl == 0) {
        out[ray * 3 + 0]      = bg0 + pr;
        out[ray * 3 + 1]      = bg1 + pg;
        out[ray * 3 + 2]      = bg2 + pb;
        out[N_RAYS * 3 + ray] = invd;
    }
}

__global__ __launch_bounds__(256, 2)
void neus_render_kernel(const float* __restrict__ sdf,
                        const float* __restrict__ color,
                        const float* __restrict__ z_vals,
                        const float* __restrict__ s_ptr,
                        const float* __restrict__ bg,
                        float* __restrict__ out)
{
    const int lane = threadIdx.x & 31;
    const int sl   = lane & 15;
    const int seg  = ((threadIdx.x >> 5) << 1) + (lane >> 4);   // 0..15

    const float s   = __ldg(s_ptr);
    const float bg0 = __ldg(bg + 0);
    const float bg1 = __ldg(bg + 1);
    const float bg2 = __ldg(bg + 2);

    const float4* sp    = reinterpret_cast<const float4*>(sdf);
    const float4* zp    = reinterpret_cast<const float4*>(z_vals);
    const float4* cbase = reinterpret_cast<const float4*>(color);

    const int stride = gridDim.x;

    int t = blockIdx.x;
    if (t >= N_TILES) return;

    // prologue: load first tile
    TileRegs cur = load_tile(sp, zp, cbase, t * RAYS_PER_TILE + seg, sl);

    for (;;) {
        const int nt = t + stride;
        const bool has_next = (nt < N_TILES);

        // issue ALL next-tile loads BEFORE touching current tile's data:
        // cross-iteration prefetch keeps 10 LDG.128 in flight per warp.
        TileRegs nxt;
        if (has_next)
            nxt = load_tile(sp, zp, cbase, nt * RAYS_PER_TILE + seg, sl);

        process_tile(cur, t * RAYS_PER_TILE + seg, sl, s, bg0, bg1, bg2, out);

        if (!has_next) break;
        cur = nxt;
        t = nt;
    }
}

extern "C" void kernel_launch(void* const* d_in, const int* in_sizes, int n_in,
                              void* d_out, int out_size)
{
    const float* sdf   = (const float*)d_in[0];
    const float* color = (const float*)d_in[1];
    const float* z     = (const float*)d_in[2];
    const float* s     = (const float*)d_in[3];
    const float* bg    = (const float*)d_in[4];
    float* out = (float*)d_out;

    // Size the persistent grid to exact residency: SMs x max-resident-blocks.
    // Pure host-side queries (no allocation, no stream ops) — capture-safe,
    // deterministic for a fixed device.
    int dev = 0, sms = 148, bpsm = 2;
    cudaGetDevice(&dev);
    cudaDeviceGetAttribute(&sms, cudaDevAttrMultiProcessorCount, dev);
    cudaOccupancyMaxActiveBlocksPerMultiprocessor(&bpsm, neus_render_kernel, 256, 0);
    if (bpsm < 1) bpsm = 1;
    int grid = sms * bpsm;
    if (grid > N_TILES) grid = N_TILES;

    neus_render_kernel<<<grid, 256>>>(sdf, color, z, s, bg, out);
}